// round 10
// baseline (speedup 1.0000x reference)
#include <cuda_runtime.h>

#define N_NODES 10000
#define KK1 10
#define KK2 25
#define DIM 64
#define OUTD 128
#define NGRAPH 64
#define NSLOT 2
#define GRID 148

typedef unsigned long long ull;

__device__ float g_Seg[NGRAPH * OUTD];
__device__ unsigned g_count;            // monotonic barrier counter (never reset)

__device__ __forceinline__ void ffma2(ull& acc, ull a, ull b) {
    asm("fma.rn.f32x2 %0, %1, %2, %0;" : "+l"(acc) : "l"(a), "l"(b));
}
__device__ __forceinline__ float f2sum(ull v) {
    return __uint_as_float((unsigned)v) + __uint_as_float((unsigned)(v >> 32));
}
__device__ __forceinline__ unsigned smem_u32(const void* p) {
    unsigned a;
    asm("{ .reg .u64 t; cvta.to.shared.u64 t, %1; cvt.u32.u64 %0, t; }"
        : "=r"(a) : "l"(p));
    return a;
}
__device__ __forceinline__ void mbar_init(unsigned addr, unsigned cnt) {
    asm volatile("mbarrier.init.shared.b64 [%0], %1;" :: "r"(addr), "r"(cnt) : "memory");
}
__device__ __forceinline__ void mbar_arrive(unsigned addr) {
    asm volatile("mbarrier.arrive.release.cta.shared::cta.b64 _, [%0];" :: "r"(addr) : "memory");
}
__device__ __forceinline__ void mbar_wait(unsigned addr, int phase) {
    asm volatile(
        "{\n\t.reg .pred P;\n\t"
        "WL_%=:\n\t"
        "mbarrier.try_wait.parity.acquire.cta.shared::cta.b64 P, [%0], %1, 0x989680;\n\t"
        "@P bra.uni WD_%=;\n\t"
        "bra.uni WL_%=;\n\t"
        "WD_%=:\n\t}"
        :: "r"(addr), "r"(phase) : "memory");
}

// Device-wide barrier: monotonic counter, each barrier consumes GRID arrivals.
__device__ __forceinline__ void gsync(int t) {
    __syncthreads();
    if (t == 0) {
        __threadfence();
        const unsigned my = atomicAdd(&g_count, 1u);
        const unsigned target = (my / GRID + 1u) * GRID;
        for (;;) {
            unsigned v;
            asm volatile("ld.global.acquire.gpu.u32 %0, [%1];"
                         : "=r"(v) : "l"(&g_count));
            if (v >= target) break;
            __nanosleep(128);
        }
        __threadfence();
    }
    __syncthreads();
}

#define W0T_LD 132              // conflict-free LDS.128 reads
#define W1T_LD 260              // conflict-free LDS.128 reads
#define XS_NODE 1408            // 11 * 128
#define XS_PAIR 2816

// smem float offsets (total 57,864 floats = 231,456 B <= 232,448)
#define OFF_W0T  8
#define OFF_W1T  (OFF_W0T + 128 * W0T_LD)      // 16904
#define OFF_RING (OFF_W1T + 128 * W1T_LD)      // 50184
#define OFF_XRB  (OFF_RING + NSLOT * XS_PAIR)  // 55816
#define SM_FLOATS (OFF_XRB + 8 * 256)          // 57864

// ---------------------------------------------------------------------------
// Single fused persistent kernel. Warp-specialized main loop:
//   warps 0-3  (t<128): consumers — GEMM1 per pair, XR rows buffered in smem,
//                       batched GEMM2 (8 rows) + g_Seg atomics every 4 pairs.
//   warps 4-11 (t>=128): producers — h2/h1/h0 streaming into 2-slot ring.
// gsync only for g_Seg zeroing (start) and before the readout (end).
// ---------------------------------------------------------------------------
extern "C" __global__ void __launch_bounds__(384, 1)
kFused(const float* __restrict__ h0, const float* __restrict__ h1,
       const float* __restrict__ h2, const float* __restrict__ w0,
       const float* __restrict__ b0, const float* __restrict__ w1,
       const float* __restrict__ b1, const int* __restrict__ gid,
       const float* __restrict__ wr1, const float* __restrict__ br1,
       const float* __restrict__ wr2, const float* __restrict__ br2,
       const float* __restrict__ wr3, const float* __restrict__ br3,
       float* __restrict__ out)
{
    extern __shared__ float sm[];
    float* w0Ts = sm + OFF_W0T;
    float* w1Ts = sm + OFF_W1T;
    float* ring = sm + OFF_RING;
    float* XRb  = sm + OFF_XRB;

    const int t   = threadIdx.x;
    const int bid = blockIdx.x;
    const unsigned mb = smem_u32(sm);

    if (t == 0) {
        #pragma unroll
        for (int s = 0; s < NSLOT; ++s) {
            mbar_init(mb + s * 16, 256);       // full: 256 producer arrivals
            mbar_init(mb + s * 16 + 8, 128);   // empty: 128 consumer arrivals
        }
    }

    // Zero segment accumulator.
    if (bid < 22) {
        const int idx = bid * 384 + t;
        if (idx < NGRAPH * OUTD) g_Seg[idx] = 0.f;
    }

    // Stage w0T, w1T: scalar, lane = column -> coalesced gmem, 4-way smem max.
    for (int i = t; i < 128 * 128; i += 384) {
        const int c = i & 127, k = i >> 7;
        w0Ts[c * W0T_LD + k] = __ldg(w0 + k * 128 + c);
    }
    for (int i = t; i < 256 * 128; i += 384) {
        const int c = i & 127, k = i >> 7;
        w1Ts[c * W1T_LD + k] = __ldg(w1 + k * 128 + c);
    }

    gsync(t);   // g_Seg zero + staging + mbar init visible block/device-wide

    if (t >= 128) {
        // ===================== PRODUCER =====================
        const int p = t - 128;               // 0..255
        int slot = 0, ph = 1;                // empty passes immediately round 1
        for (int np = bid * 2; np < N_NODES; np += GRID * 2) {
            mbar_wait(mb + slot * 16 + 8, ph);
            float* Xb = ring + slot * XS_PAIR;

            #pragma unroll
            for (int pass = 0; pass < 2; ++pass) {
                const int task = p + pass * 256;
                if (task < 320) {
                    const int node = task / 160;
                    const int rem  = task - node * 160;
                    const int j    = rem >> 4;
                    const int c4   = rem & 15;
                    const int base = (np + node) * KK1 + j;
                    const float4* q = (const float4*)(h2 + base * (KK2 * DIM)) + c4;
                    float4 s0 = make_float4(0.f, 0.f, 0.f, 0.f);
                    float4 s1 = make_float4(0.f, 0.f, 0.f, 0.f);
                    #pragma unroll
                    for (int k = 0; k < 24; k += 2) {
                        const float4 a = __ldg(q + k * 16);
                        const float4 b = __ldg(q + (k + 1) * 16);
                        s0.x += a.x; s0.y += a.y; s0.z += a.z; s0.w += a.w;
                        s1.x += b.x; s1.y += b.y; s1.z += b.z; s1.w += b.w;
                    }
                    const float4 a = __ldg(q + 24 * 16);
                    s0.x += a.x; s0.y += a.y; s0.z += a.z; s0.w += a.w;
                    float4* xrow = (float4*)(Xb + node * XS_NODE + j * 128);
                    xrow[16 + c4] = make_float4((s0.x + s1.x) * 0.04f,
                                                (s0.y + s1.y) * 0.04f,
                                                (s0.z + s1.z) * 0.04f,
                                                (s0.w + s1.w) * 0.04f);
                    xrow[c4] = __ldg((const float4*)(h1 + base * DIM) + c4);
                } else if (task < 352) {
                    const int idx = task - 320;
                    const int node = idx >> 4, c4 = idx & 15;
                    ((float4*)(Xb + node * XS_NODE + 10 * 128))[c4] =
                        __ldg((const float4*)(h0 + (np + node) * DIM) + c4);
                } else if (task < 384) {
                    const int idx = task - 352;
                    const int node = idx >> 4, c4 = idx & 15;
                    const float4* q = (const float4*)(h1 + (np + node) * KK1 * DIM) + c4;
                    float4 s = make_float4(0.f, 0.f, 0.f, 0.f);
                    #pragma unroll
                    for (int j = 0; j < KK1; ++j) {
                        const float4 v = __ldg(q + j * 16);
                        s.x += v.x; s.y += v.y; s.z += v.z; s.w += v.w;
                    }
                    ((float4*)(Xb + node * XS_NODE + 10 * 128))[16 + c4] =
                        make_float4(s.x * 0.1f, s.y * 0.1f, s.z * 0.1f, s.w * 0.1f);
                }
            }
            mbar_arrive(mb + slot * 16);            // full
            if (++slot == NSLOT) { slot = 0; ph ^= 1; }
        }
    } else {
        // ===================== CONSUMER =====================
        const int node = t >> 6;                   // 0/1; doubles as GEMM2 rgroup
        const int col  = t & 63;                   // owns cols (col, col+64)
        const ulonglong2* wpa = (const ulonglong2*)(w0Ts + col * W0T_LD);
        const ulonglong2* wpb = (const ulonglong2*)(w0Ts + (col + 64) * W0T_LD);
        const ulonglong2* vpa = (const ulonglong2*)(w1Ts + col * W1T_LD);
        const ulonglong2* vpb = (const ulonglong2*)(w1Ts + (col + 64) * W1T_LD);
        const float bbA = __ldg(b0 + col);
        const float bbB = __ldg(b0 + col + 64);
        const float cbA = __ldg(b1 + col);
        const float cbB = __ldg(b1 + col + 64);

        int slot = 0, ph = 0;
        int bfill = 0;
        int npb = bid * 2;    // first node of current batch

        // batched GEMM2 over XRb rows [0, 2*nv): 4 rows x 2 cols per thread
        auto gemm2 = [&](int npbase, int nv) {
            asm volatile("bar.sync 1, 128;" ::: "memory");   // XRb writes visible
            ull acc[8];
            #pragma unroll
            for (int r = 0; r < 8; ++r) acc[r] = 0ull;

            const float* xb = XRb + (node * 4) * 256;
            #pragma unroll 2
            for (int kq = 0; kq < 64; ++kq) {
                const ulonglong2 wv0 = vpa[kq];
                const ulonglong2 wv1 = vpb[kq];
                #pragma unroll
                for (int rr = 0; rr < 4; ++rr) {
                    const ulonglong2 x = *(const ulonglong2*)(xb + rr * 256 + kq * 4);
                    ffma2(acc[2 * rr],     x.x, wv0.x);
                    ffma2(acc[2 * rr],     x.y, wv0.y);
                    ffma2(acc[2 * rr + 1], x.x, wv1.x);
                    ffma2(acc[2 * rr + 1], x.y, wv1.y);
                }
            }
            #pragma unroll
            for (int q = 0; q < 2; ++q) {
                const int pidx = node * 2 + q;       // pair index in batch
                if (pidx < nv) {
                    const int n0 = npbase + pidx * (GRID * 2);
                    const float y00 = fmaxf(f2sum(acc[4 * q])     + cbA, 0.f);
                    const float y01 = fmaxf(f2sum(acc[4 * q + 1]) + cbB, 0.f);
                    const float y10 = fmaxf(f2sum(acc[4 * q + 2]) + cbA, 0.f);
                    const float y11 = fmaxf(f2sum(acc[4 * q + 3]) + cbB, 0.f);
                    const int g0 = __ldg(gid + n0);
                    const int g1 = __ldg(gid + n0 + 1);
                    if (g0 == g1) {
                        atomicAdd(&g_Seg[g0 * OUTD + col],      y00 + y10);
                        atomicAdd(&g_Seg[g0 * OUTD + col + 64], y01 + y11);
                    } else {
                        atomicAdd(&g_Seg[g0 * OUTD + col],      y00);
                        atomicAdd(&g_Seg[g0 * OUTD + col + 64], y01);
                        atomicAdd(&g_Seg[g1 * OUTD + col],      y10);
                        atomicAdd(&g_Seg[g1 * OUTD + col + 64], y11);
                    }
                }
            }
            asm volatile("bar.sync 1, 128;" ::: "memory");   // safe to reuse XRb
        };

        for (int np = bid * 2; np < N_NODES; np += GRID * 2) {
            mbar_wait(mb + slot * 16, ph);          // full
            const float* X = ring + slot * XS_PAIR + node * XS_NODE;

            // --- GEMM1: Y = relu(X @ w0 + b0), 2 cols/thread ---
            ull accA[11], accB[11];
            #pragma unroll
            for (int r = 0; r < 11; ++r) { accA[r] = 0ull; accB[r] = 0ull; }

            #pragma unroll 2
            for (int kq = 0; kq < 32; ++kq) {
                const ulonglong2 wa = wpa[kq];
                const ulonglong2 wb = wpb[kq];
                #pragma unroll
                for (int r = 0; r < 11; ++r) {
                    const ulonglong2 x = *(const ulonglong2*)(X + r * 128 + kq * 4);
                    ffma2(accA[r], x.x, wa.x);
                    ffma2(accA[r], x.y, wa.y);
                    ffma2(accB[r], x.x, wb.x);
                    ffma2(accB[r], x.y, wb.y);
                }
            }

            float ymA = 0.f, ymB = 0.f;
            #pragma unroll
            for (int r = 0; r < KK1; ++r) {
                ymA += fmaxf(f2sum(accA[r]) + bbA, 0.f);
                ymB += fmaxf(f2sum(accB[r]) + bbB, 0.f);
            }
            const float a01A = fmaxf(f2sum(accA[10]) + bbA, 0.f);
            const float a01B = fmaxf(f2sum(accB[10]) + bbB, 0.f);

            // stage XR row pair into batch buffer
            float* xr = XRb + (2 * bfill + node) * 256;
            xr[col]            = a01A;
            xr[col + 64]       = a01B;
            xr[128 + col]      = ymA * 0.1f;
            xr[128 + col + 64] = ymB * 0.1f;

            mbar_arrive(mb + slot * 16 + 8);        // empty (free ring ASAP)
            if (++slot == NSLOT) { slot = 0; ph ^= 1; }

            if (++bfill == 4) {
                gemm2(npb, 4);
                bfill = 0;
                npb = np + GRID * 2;
            }
        }
        if (bfill > 0) gemm2(npb, bfill);
    }

    gsync(t);   // all seg atomics visible

    // ======================= READOUT (blocks 0..63) =======================
    if (bid < NGRAPH) {
        float* r1s = sm;
        float* r2s = sm + 35;
        const int g = bid;
        const float SC = 1.0507009873554805f;
        const float AL = 1.6732632423543772f;

        if (t < 35) {
            float acc = br1[t];
            #pragma unroll 4
            for (int k = 0; k < OUTD; ++k)
                acc = fmaf(g_Seg[g * OUTD + k], wr1[k * 35 + t], acc);
            r1s[t] = (acc > 0.f) ? SC * acc : SC * AL * (expf(acc) - 1.f);
        }
        __syncthreads();

        if (t < 35) {
            float acc = br2[t];
            #pragma unroll
            for (int k = 0; k < 35; ++k)
                acc = fmaf(r1s[k], wr2[k * 35 + t], acc);
            r2s[t] = (acc > 0.f) ? SC * acc : SC * AL * (expf(acc) - 1.f);
        }
        __syncthreads();

        if (t == 0) {
            float acc = br3[0];
            #pragma unroll
            for (int k = 0; k < 35; ++k)
                acc = fmaf(r2s[k], wr3[k], acc);
            out[g] = acc;
        }
    }
}

// ---------------------------------------------------------------------------
extern "C" void kernel_launch(void* const* d_in, const int* in_sizes, int n_in,
                              void* d_out, int out_size)
{
    const float* h0  = (const float*)d_in[0];
    const float* h1  = (const float*)d_in[1];
    const float* h2  = (const float*)d_in[2];
    const float* w0  = (const float*)d_in[3];
    const float* b0  = (const float*)d_in[4];
    const float* w1  = (const float*)d_in[5];
    const float* b1  = (const float*)d_in[6];
    const float* wr1 = (const float*)d_in[7];
    const float* br1 = (const float*)d_in[8];
    const float* wr2 = (const float*)d_in[9];
    const float* br2 = (const float*)d_in[10];
    const float* wr3 = (const float*)d_in[11];
    const float* br3 = (const float*)d_in[12];
    const int*   gid = (const int*)d_in[13];

    const int smF = SM_FLOATS * 4;   // 231,456 B
    cudaFuncSetAttribute(kFused, cudaFuncAttributeMaxDynamicSharedMemorySize, smF);

    kFused<<<GRID, 384, smF>>>(h0, h1, h2, w0, b0, w1, b1, gid,
                               wr1, br1, wr2, br2, wr3, br3, (float*)d_out);
}

// round 11
// speedup vs baseline: 1.0677x; 1.0677x over previous
#include <cuda_runtime.h>

#define N_NODES 10000
#define KK1 10
#define KK2 25
#define DIM 64
#define OUTD 128
#define NGRAPH 64
#define NSLOT 4
#define GRID 148

typedef unsigned long long ull;

__device__ float g_Seg[NGRAPH * OUTD];
__device__ unsigned g_count;            // monotonic barrier counter (never reset)

__device__ __forceinline__ void ffma2(ull& acc, ull a, ull b) {
    asm("fma.rn.f32x2 %0, %1, %2, %0;" : "+l"(acc) : "l"(a), "l"(b));
}
__device__ __forceinline__ float f2sum(ull v) {
    return __uint_as_float((unsigned)v) + __uint_as_float((unsigned)(v >> 32));
}
__device__ __forceinline__ unsigned smem_u32(const void* p) {
    unsigned a;
    asm("{ .reg .u64 t; cvta.to.shared.u64 t, %1; cvt.u32.u64 %0, t; }"
        : "=r"(a) : "l"(p));
    return a;
}
__device__ __forceinline__ void mbar_init(unsigned addr, unsigned cnt) {
    asm volatile("mbarrier.init.shared.b64 [%0], %1;" :: "r"(addr), "r"(cnt) : "memory");
}
__device__ __forceinline__ void mbar_arrive(unsigned addr) {
    asm volatile("mbarrier.arrive.release.cta.shared::cta.b64 _, [%0];" :: "r"(addr) : "memory");
}
__device__ __forceinline__ void mbar_wait(unsigned addr, int phase) {
    asm volatile(
        "{\n\t.reg .pred P;\n\t"
        "WL_%=:\n\t"
        "mbarrier.try_wait.parity.acquire.cta.shared::cta.b64 P, [%0], %1, 0x989680;\n\t"
        "@P bra.uni WD_%=;\n\t"
        "bra.uni WL_%=;\n\t"
        "WD_%=:\n\t}"
        :: "r"(addr), "r"(phase) : "memory");
}

// Device-wide barrier: monotonic counter, each barrier consumes GRID arrivals.
__device__ __forceinline__ void gsync(int t) {
    __syncthreads();
    if (t == 0) {
        __threadfence();
        const unsigned my = atomicAdd(&g_count, 1u);
        const unsigned target = (my / GRID + 1u) * GRID;
        for (;;) {
            unsigned v;
            asm volatile("ld.global.acquire.gpu.u32 %0, [%1];"
                         : "=r"(v) : "l"(&g_count));
            if (v >= target) break;
            __nanosleep(128);
        }
        __threadfence();
    }
    __syncthreads();
}

#define W0T_LD 132              // conflict-free LDS.128 reads
#define W1T_LD 260              // conflict-free LDS.128 reads
#define XS_NODE 1408            // 11 * 128
#define XS_PAIR 2816
#define MAXROWS 68              // max XR rows per block (34 pairs)

// smem float offsets
#define OFF_XRS 16                              // after 64B of mbarriers
#define OFF_LOW (OFF_XRS + MAXROWS * 256)       // 17424
// phase-1 overlay: w0T @ OFF_LOW (16896), b0s (+128), ring (+NSLOT*2816)
// phase-2 overlay: w1T @ OFF_LOW (33280), sgid (+68)
#define SM_FLOATS (OFF_LOW + 33280 + 68)        // 50772 -> 203,088 B

// ---------------------------------------------------------------------------
// Fused persistent kernel, block-local phase 2.
// ---------------------------------------------------------------------------
extern "C" __global__ void __launch_bounds__(384, 1)
kFused(const float* __restrict__ h0, const float* __restrict__ h1,
       const float* __restrict__ h2, const float* __restrict__ w0,
       const float* __restrict__ b0, const float* __restrict__ w1,
       const float* __restrict__ b1, const int* __restrict__ gid,
       const float* __restrict__ wr1, const float* __restrict__ br1,
       const float* __restrict__ wr2, const float* __restrict__ br2,
       const float* __restrict__ wr3, const float* __restrict__ br3,
       float* __restrict__ out)
{
    extern __shared__ float sm[];
    float* XRs = sm + OFF_XRS;

    const int t   = threadIdx.x;
    const int bid = blockIdx.x;
    const unsigned mb = smem_u32(sm);

    // ---------- prologue ----------
    if (t == 0) {
        #pragma unroll
        for (int s = 0; s < NSLOT; ++s) {
            mbar_init(mb + s * 16, 256);       // full: 256 producer arrivals
            mbar_init(mb + s * 16 + 8, 128);   // empty: 128 consumer arrivals
        }
    }
    if (bid < 22) {
        const int idx = bid * 384 + t;
        if (idx < NGRAPH * OUTD) g_Seg[idx] = 0.f;
    }
    {   // stage w0 transposed (scalar: coalesced LDG, 4-way-max STS)
        float* w0Ts = sm + OFF_LOW;
        float* b0s  = w0Ts + 16896;
        for (int i = t; i < 128 * 128; i += 384) {
            const int c = i & 127, k = i >> 7;
            w0Ts[c * W0T_LD + k] = __ldg(w0 + k * 128 + c);
        }
        if (t < 128) b0s[t] = b0[t];
    }
    gsync(t);   // g_Seg zeroing visible device-wide before ANY phase-2 atomics

    // ======================= PHASE 1 (proven kA) =======================
    {
        float* w0Ts = sm + OFF_LOW;
        float* b0s  = w0Ts + 16896;
        float* ring = b0s + 128;

        if (t >= 128) {
            // -------- producer --------
            const int p = t - 128;
            int slot = 0, ph = 1;
            for (int np = bid * 2; np < N_NODES; np += GRID * 2) {
                mbar_wait(mb + slot * 16 + 8, ph);
                float* Xb = ring + slot * XS_PAIR;

                #pragma unroll
                for (int pass = 0; pass < 2; ++pass) {
                    const int task = p + pass * 256;
                    if (task < 320) {
                        const int node = task / 160;
                        const int rem  = task - node * 160;
                        const int j    = rem >> 4;
                        const int c4   = rem & 15;
                        const int base = (np + node) * KK1 + j;
                        const float4* q = (const float4*)(h2 + base * (KK2 * DIM)) + c4;
                        float4 s0 = make_float4(0.f, 0.f, 0.f, 0.f);
                        float4 s1 = make_float4(0.f, 0.f, 0.f, 0.f);
                        #pragma unroll
                        for (int k = 0; k < 24; k += 2) {
                            const float4 a = __ldg(q + k * 16);
                            const float4 b = __ldg(q + (k + 1) * 16);
                            s0.x += a.x; s0.y += a.y; s0.z += a.z; s0.w += a.w;
                            s1.x += b.x; s1.y += b.y; s1.z += b.z; s1.w += b.w;
                        }
                        const float4 a = __ldg(q + 24 * 16);
                        s0.x += a.x; s0.y += a.y; s0.z += a.z; s0.w += a.w;
                        float4* xrow = (float4*)(Xb + node * XS_NODE + j * 128);
                        xrow[16 + c4] = make_float4((s0.x + s1.x) * 0.04f,
                                                    (s0.y + s1.y) * 0.04f,
                                                    (s0.z + s1.z) * 0.04f,
                                                    (s0.w + s1.w) * 0.04f);
                        xrow[c4] = __ldg((const float4*)(h1 + base * DIM) + c4);
                    } else if (task < 352) {
                        const int idx = task - 320;
                        const int node = idx >> 4, c4 = idx & 15;
                        ((float4*)(Xb + node * XS_NODE + 10 * 128))[c4] =
                            __ldg((const float4*)(h0 + (np + node) * DIM) + c4);
                    } else if (task < 384) {
                        const int idx = task - 352;
                        const int node = idx >> 4, c4 = idx & 15;
                        const float4* q = (const float4*)(h1 + (np + node) * KK1 * DIM) + c4;
                        float4 s = make_float4(0.f, 0.f, 0.f, 0.f);
                        #pragma unroll
                        for (int j = 0; j < KK1; ++j) {
                            const float4 v = __ldg(q + j * 16);
                            s.x += v.x; s.y += v.y; s.z += v.z; s.w += v.w;
                        }
                        ((float4*)(Xb + node * XS_NODE + 10 * 128))[16 + c4] =
                            make_float4(s.x * 0.1f, s.y * 0.1f, s.z * 0.1f, s.w * 0.1f);
                    }
                }
                mbar_arrive(mb + slot * 16);
                if (++slot == NSLOT) { slot = 0; ph ^= 1; }
            }
        } else {
            // -------- consumer (2 cols/thread), XR rows -> smem --------
            const int node = t >> 6;
            const int col  = t & 63;
            const ulonglong2* wpa = (const ulonglong2*)(w0Ts + col * W0T_LD);
            const ulonglong2* wpb = (const ulonglong2*)(w0Ts + (col + 64) * W0T_LD);
            const float bbA = b0s[col];
            const float bbB = b0s[col + 64];

            int slot = 0, ph = 0, ip = 0;
            for (int np = bid * 2; np < N_NODES; np += GRID * 2) {
                mbar_wait(mb + slot * 16, ph);
                const float* X = ring + slot * XS_PAIR + node * XS_NODE;

                ull accA[11], accB[11];
                #pragma unroll
                for (int r = 0; r < 11; ++r) { accA[r] = 0ull; accB[r] = 0ull; }

                #pragma unroll 2
                for (int kq = 0; kq < 32; ++kq) {
                    const ulonglong2 wa = wpa[kq];
                    const ulonglong2 wb = wpb[kq];
                    #pragma unroll
                    for (int r = 0; r < 11; ++r) {
                        const ulonglong2 x = *(const ulonglong2*)(X + r * 128 + kq * 4);
                        ffma2(accA[r], x.x, wa.x);
                        ffma2(accA[r], x.y, wa.y);
                        ffma2(accB[r], x.x, wb.x);
                        ffma2(accB[r], x.y, wb.y);
                    }
                }

                float ymA = 0.f, ymB = 0.f;
                #pragma unroll
                for (int r = 0; r < KK1; ++r) {
                    ymA += fmaxf(f2sum(accA[r]) + bbA, 0.f);
                    ymB += fmaxf(f2sum(accB[r]) + bbB, 0.f);
                }
                const float a01A = fmaxf(f2sum(accA[10]) + bbA, 0.f);
                const float a01B = fmaxf(f2sum(accB[10]) + bbB, 0.f);

                float* xr = XRs + (2 * ip + node) * 256;
                xr[col]            = a01A;
                xr[col + 64]       = a01B;
                xr[128 + col]      = ymA * 0.1f;
                xr[128 + col + 64] = ymB * 0.1f;

                mbar_arrive(mb + slot * 16 + 8);
                if (++slot == NSLOT) { slot = 0; ph ^= 1; }
                ++ip;
            }
        }
    }

    __syncthreads();   // phase 1 done block-locally; ring/w0T now dead

    // ============ PHASE 2 (block-local): relu(XR@w1+b1) -> seg atomics ============
    {
        float* w1Ts = sm + OFF_LOW;                 // [128][260]
        int*   sgid = (int*)(sm + OFF_LOW + 33280); // 68 ints

        const int npairs = (N_NODES - bid * 2 + GRID * 2 - 1) / (GRID * 2);
        const int nrows  = 2 * npairs;

        // Restage w1 transposed: coalesced scalar LDG x4, conflict-free STS.128.
        for (int i = t; i < 8192; i += 384) {
            const int c = i & 127, kq = i >> 7;       // kq: float4 group of k
            float4 v;
            v.x = __ldg(w1 + (kq * 4 + 0) * 128 + c);
            v.y = __ldg(w1 + (kq * 4 + 1) * 128 + c);
            v.z = __ldg(w1 + (kq * 4 + 2) * 128 + c);
            v.w = __ldg(w1 + (kq * 4 + 3) * 128 + c);
            ((float4*)(w1Ts + c * W1T_LD))[kq] = v;
        }
        if (t < nrows)
            sgid[t] = __ldg(gid + bid * 2 + (t >> 1) * (GRID * 2) + (t & 1));
        __syncthreads();

        const int cb = t & 63;                      // cols cb, cb+64
        const int rb = t >> 6;                      // row-block 0..5 (12 rows)
        const float cbA = __ldg(b1 + cb);
        const float cbB = __ldg(b1 + cb + 64);
        const ulonglong2* wp0 = (const ulonglong2*)(w1Ts + cb * W1T_LD);
        const ulonglong2* wp1 = (const ulonglong2*)(w1Ts + (cb + 64) * W1T_LD);

        ull acc[24];
        #pragma unroll
        for (int r = 0; r < 24; ++r) acc[r] = 0ull;

        const float* xb = XRs + (rb * 12) * 256;
        #pragma unroll 1
        for (int kq = 0; kq < 64; ++kq) {
            const ulonglong2 wv0 = wp0[kq];
            const ulonglong2 wv1 = wp1[kq];
            #pragma unroll
            for (int rr = 0; rr < 12; ++rr) {
                const ulonglong2 x = *(const ulonglong2*)(xb + rr * 256 + kq * 4);
                ffma2(acc[2 * rr],     x.x, wv0.x);
                ffma2(acc[2 * rr],     x.y, wv0.y);
                ffma2(acc[2 * rr + 1], x.x, wv1.x);
                ffma2(acc[2 * rr + 1], x.y, wv1.y);
            }
        }

        // relu + run-length coalesced atomics (pairs share gid ~always)
        int curg = (rb * 12 < nrows) ? sgid[rb * 12] : -1;
        float s0 = 0.f, s1 = 0.f;
        #pragma unroll
        for (int rr = 0; rr < 12; ++rr) {
            const int row = rb * 12 + rr;
            if (row < nrows) {
                const float y0 = fmaxf(f2sum(acc[2 * rr])     + cbA, 0.f);
                const float y1 = fmaxf(f2sum(acc[2 * rr + 1]) + cbB, 0.f);
                const int g = sgid[row];
                if (g != curg) {
                    if (curg >= 0) {
                        atomicAdd(&g_Seg[curg * OUTD + cb],      s0);
                        atomicAdd(&g_Seg[curg * OUTD + cb + 64], s1);
                    }
                    s0 = 0.f; s1 = 0.f; curg = g;
                }
                s0 += y0; s1 += y1;
            }
        }
        if (curg >= 0) {
            atomicAdd(&g_Seg[curg * OUTD + cb],      s0);
            atomicAdd(&g_Seg[curg * OUTD + cb + 64], s1);
        }
    }

    gsync(t);   // all seg atomics visible

    // ======================= READOUT (blocks 0..63) =======================
    if (bid < NGRAPH) {
        float* r1s = sm;
        float* r2s = sm + 35;
        const int g = bid;
        const float SC = 1.0507009873554805f;
        const float AL = 1.6732632423543772f;

        if (t < 35) {
            float acc = br1[t];
            #pragma unroll 4
            for (int k = 0; k < OUTD; ++k)
                acc = fmaf(g_Seg[g * OUTD + k], wr1[k * 35 + t], acc);
            r1s[t] = (acc > 0.f) ? SC * acc : SC * AL * (expf(acc) - 1.f);
        }
        __syncthreads();

        if (t < 35) {
            float acc = br2[t];
            #pragma unroll
            for (int k = 0; k < 35; ++k)
                acc = fmaf(r1s[k], wr2[k * 35 + t], acc);
            r2s[t] = (acc > 0.f) ? SC * acc : SC * AL * (expf(acc) - 1.f);
        }
        __syncthreads();

        if (t == 0) {
            float acc = br3[0];
            #pragma unroll
            for (int k = 0; k < 35; ++k)
                acc = fmaf(r2s[k], wr3[k], acc);
            out[g] = acc;
        }
    }
}

// ---------------------------------------------------------------------------
extern "C" void kernel_launch(void* const* d_in, const int* in_sizes, int n_in,
                              void* d_out, int out_size)
{
    const float* h0  = (const float*)d_in[0];
    const float* h1  = (const float*)d_in[1];
    const float* h2  = (const float*)d_in[2];
    const float* w0  = (const float*)d_in[3];
    const float* b0  = (const float*)d_in[4];
    const float* w1  = (const float*)d_in[5];
    const float* b1  = (const float*)d_in[6];
    const float* wr1 = (const float*)d_in[7];
    const float* br1 = (const float*)d_in[8];
    const float* wr2 = (const float*)d_in[9];
    const float* br2 = (const float*)d_in[10];
    const float* wr3 = (const float*)d_in[11];
    const float* br3 = (const float*)d_in[12];
    const int*   gid = (const int*)d_in[13];

    const int smF = SM_FLOATS * 4;   // 203,088 B
    cudaFuncSetAttribute(kFused, cudaFuncAttributeMaxDynamicSharedMemorySize, smF);

    kFused<<<GRID, 384, smF>>>(h0, h1, h2, w0, b0, w1, b1, gid,
                               wr1, br1, wr2, br2, wr3, br3, (float*)d_out);
}

// round 12
// speedup vs baseline: 1.2971x; 1.2149x over previous
#include <cuda_runtime.h>

#define N_NODES 10000
#define KK1 10
#define KK2 25
#define DIM 64
#define OUTD 128
#define NGRAPH 64
#define NSLOT 4
#define GRID 148

typedef unsigned long long ull;

__device__ float g_XR[N_NODES * 256];   // per node0: [a01(128) | mean_relu_a12(128)]
__device__ float g_Seg[NGRAPH * OUTD];

__device__ __forceinline__ void ffma2(ull& acc, ull a, ull b) {
    asm("fma.rn.f32x2 %0, %1, %2, %0;" : "+l"(acc) : "l"(a), "l"(b));
}
__device__ __forceinline__ float f2sum(ull v) {
    return __uint_as_float((unsigned)v) + __uint_as_float((unsigned)(v >> 32));
}
__device__ __forceinline__ unsigned smem_u32(const void* p) {
    unsigned a;
    asm("{ .reg .u64 t; cvta.to.shared.u64 t, %1; cvt.u32.u64 %0, t; }"
        : "=r"(a) : "l"(p));
    return a;
}
__device__ __forceinline__ void mbar_init(unsigned addr, unsigned cnt) {
    asm volatile("mbarrier.init.shared.b64 [%0], %1;" :: "r"(addr), "r"(cnt) : "memory");
}
__device__ __forceinline__ void mbar_arrive(unsigned addr) {
    asm volatile("mbarrier.arrive.release.cta.shared::cta.b64 _, [%0];" :: "r"(addr) : "memory");
}
__device__ __forceinline__ void mbar_wait(unsigned addr, int phase) {
    asm volatile(
        "{\n\t.reg .pred P;\n\t"
        "WL_%=:\n\t"
        "mbarrier.try_wait.parity.acquire.cta.shared::cta.b64 P, [%0], %1, 0x989680;\n\t"
        "@P bra.uni WD_%=;\n\t"
        "bra.uni WL_%=;\n\t"
        "WD_%=:\n\t}"
        :: "r"(addr), "r"(phase) : "memory");
}

#define W0T_LD 132
#define W1T_LD 260
#define XS_NODE 1408
#define XS_PAIR 2816

// ---------------------------------------------------------------------------
// Kernel A: EXACT copy of the proven 138.5us config (R5/R7).
// ---------------------------------------------------------------------------
extern "C" __global__ void __launch_bounds__(384, 1)
kA(const float* __restrict__ h0, const float* __restrict__ h1,
   const float* __restrict__ h2, const float* __restrict__ w0,
   const float* __restrict__ b0)
{
    extern __shared__ float sm[];
    float* w0Ts = sm + 8;                  // [128 cols][132]
    float* b0s  = w0Ts + 16896;            // 128
    float* ring = b0s + 128;               // NSLOT * 2816

    const int t = threadIdx.x;
    const unsigned mb = smem_u32(sm);

    if (t == 0) {
        #pragma unroll
        for (int s = 0; s < NSLOT; ++s) {
            mbar_init(mb + s * 16, 256);       // full
            mbar_init(mb + s * 16 + 8, 128);   // empty
        }
    }

    // Zero segment accumulator (kB runs after kA in stream order).
    if (blockIdx.x < 22) {
        const int idx = blockIdx.x * 384 + t;
        if (idx < NGRAPH * OUTD) g_Seg[idx] = 0.f;
    }

    for (int i = t; i < 4096; i += 384) {
        const int k  = i >> 5;
        const int cq = i & 31;
        const float4 v = __ldg((const float4*)(w0 + k * 128) + cq);
        w0Ts[(cq * 4 + 0) * W0T_LD + k] = v.x;
        w0Ts[(cq * 4 + 1) * W0T_LD + k] = v.y;
        w0Ts[(cq * 4 + 2) * W0T_LD + k] = v.z;
        w0Ts[(cq * 4 + 3) * W0T_LD + k] = v.w;
    }
    if (t < 128) b0s[t] = b0[t];
    __syncthreads();

    if (t >= 128) {
        // -------- producer --------
        const int p = t - 128;
        int slot = 0, ph = 1;
        for (int np = blockIdx.x * 2; np < N_NODES; np += GRID * 2) {
            mbar_wait(mb + slot * 16 + 8, ph);
            float* Xb = ring + slot * XS_PAIR;

            #pragma unroll
            for (int pass = 0; pass < 2; ++pass) {
                const int task = p + pass * 256;
                if (task < 320) {
                    const int node = task / 160;
                    const int rem  = task - node * 160;
                    const int j    = rem >> 4;
                    const int c4   = rem & 15;
                    const int base = (np + node) * KK1 + j;
                    const float4* q = (const float4*)(h2 + base * (KK2 * DIM)) + c4;
                    float4 s0 = make_float4(0.f, 0.f, 0.f, 0.f);
                    float4 s1 = make_float4(0.f, 0.f, 0.f, 0.f);
                    #pragma unroll
                    for (int k = 0; k < 24; k += 2) {
                        const float4 a = __ldg(q + k * 16);
                        const float4 b = __ldg(q + (k + 1) * 16);
                        s0.x += a.x; s0.y += a.y; s0.z += a.z; s0.w += a.w;
                        s1.x += b.x; s1.y += b.y; s1.z += b.z; s1.w += b.w;
                    }
                    const float4 a = __ldg(q + 24 * 16);
                    s0.x += a.x; s0.y += a.y; s0.z += a.z; s0.w += a.w;
                    float4* xrow = (float4*)(Xb + node * XS_NODE + j * 128);
                    xrow[16 + c4] = make_float4((s0.x + s1.x) * 0.04f,
                                                (s0.y + s1.y) * 0.04f,
                                                (s0.z + s1.z) * 0.04f,
                                                (s0.w + s1.w) * 0.04f);
                    xrow[c4] = __ldg((const float4*)(h1 + base * DIM) + c4);
                } else if (task < 352) {
                    const int idx = task - 320;
                    const int node = idx >> 4, c4 = idx & 15;
                    ((float4*)(Xb + node * XS_NODE + 10 * 128))[c4] =
                        __ldg((const float4*)(h0 + (np + node) * DIM) + c4);
                } else if (task < 384) {
                    const int idx = task - 352;
                    const int node = idx >> 4, c4 = idx & 15;
                    const float4* q = (const float4*)(h1 + (np + node) * KK1 * DIM) + c4;
                    float4 s = make_float4(0.f, 0.f, 0.f, 0.f);
                    #pragma unroll
                    for (int j = 0; j < KK1; ++j) {
                        const float4 v = __ldg(q + j * 16);
                        s.x += v.x; s.y += v.y; s.z += v.z; s.w += v.w;
                    }
                    ((float4*)(Xb + node * XS_NODE + 10 * 128))[16 + c4] =
                        make_float4(s.x * 0.1f, s.y * 0.1f, s.z * 0.1f, s.w * 0.1f);
                }
            }
            mbar_arrive(mb + slot * 16);
            if (++slot == NSLOT) { slot = 0; ph ^= 1; }
        }
    } else {
        // -------- consumer (2 cols/thread) --------
        const int node = t >> 6;
        const int col  = t & 63;
        const ulonglong2* wpa = (const ulonglong2*)(w0Ts + col * W0T_LD);
        const ulonglong2* wpb = (const ulonglong2*)(w0Ts + (col + 64) * W0T_LD);
        const float bbA = b0s[col];
        const float bbB = b0s[col + 64];

        int slot = 0, ph = 0;
        for (int np = blockIdx.x * 2; np < N_NODES; np += GRID * 2) {
            mbar_wait(mb + slot * 16, ph);
            const float* X = ring + slot * XS_PAIR + node * XS_NODE;

            ull accA[11], accB[11];
            #pragma unroll
            for (int r = 0; r < 11; ++r) { accA[r] = 0ull; accB[r] = 0ull; }

            #pragma unroll 2
            for (int kq = 0; kq < 32; ++kq) {
                const ulonglong2 wa = wpa[kq];
                const ulonglong2 wb = wpb[kq];
                #pragma unroll
                for (int r = 0; r < 11; ++r) {
                    const ulonglong2 x = *(const ulonglong2*)(X + r * 128 + kq * 4);
                    ffma2(accA[r], x.x, wa.x);
                    ffma2(accA[r], x.y, wa.y);
                    ffma2(accB[r], x.x, wb.x);
                    ffma2(accB[r], x.y, wb.y);
                }
            }

            float ymA = 0.f, ymB = 0.f;
            #pragma unroll
            for (int r = 0; r < KK1; ++r) {
                ymA += fmaxf(f2sum(accA[r]) + bbA, 0.f);
                ymB += fmaxf(f2sum(accB[r]) + bbB, 0.f);
            }
            const float a01A = fmaxf(f2sum(accA[10]) + bbA, 0.f);
            const float a01B = fmaxf(f2sum(accB[10]) + bbB, 0.f);

            float* xr = g_XR + (np + node) * 256;
            xr[col]            = a01A;
            xr[col + 64]       = a01B;
            xr[128 + col]      = ymA * 0.1f;
            xr[128 + col + 64] = ymB * 0.1f;

            mbar_arrive(mb + slot * 16 + 8);
            if (++slot == NSLOT) { slot = 0; ph ^= 1; }
        }
    }
}

// ---------------------------------------------------------------------------
// Kernel B (v4): perfectly balanced — each block owns exactly 68 contiguous
// rows (148*68 >= 10000). 512 threads = 4 row-groups x 128 cols; thread tile
// 17 rows x 1 col in plain float accs (no spill, no FFMA2). Weights amortized
// 17 rows per LDS.128. Run-length coalesced segment atomics.
// ---------------------------------------------------------------------------
#define KB_ROWS 68
extern "C" __global__ void __launch_bounds__(512, 1)
kB(const float* __restrict__ w1, const float* __restrict__ b1,
   const int* __restrict__ gid)
{
    extern __shared__ float sm[];
    float* w1Ts = sm;                        // [128][260] = 33280 floats
    float* xs   = sm + 33280;                // 68 rows x 256 = 17408 floats
    int*   sgid = (int*)(sm + 33280 + 17408);

    const int t  = threadIdx.x;
    const int r0 = blockIdx.x * KB_ROWS;
    const int nrows = min(KB_ROWS, max(0, N_NODES - r0));

    // Stage w1 transposed: coalesced scalar LDG x4, conflict-free STS.128.
    for (int i = t; i < 8192; i += 512) {
        const int c = i & 127, kq = i >> 7;
        float4 v;
        v.x = __ldg(w1 + (kq * 4 + 0) * 128 + c);
        v.y = __ldg(w1 + (kq * 4 + 1) * 128 + c);
        v.z = __ldg(w1 + (kq * 4 + 2) * 128 + c);
        v.w = __ldg(w1 + (kq * 4 + 3) * 128 + c);
        ((float4*)(w1Ts + c * W1T_LD))[kq] = v;
    }
    // Stage this block's 68 XR rows (zero-pad beyond nrows).
    for (int i = t; i < KB_ROWS * 64; i += 512) {
        const int row = i >> 6, q = i & 63;
        ((float4*)(xs + row * 256))[q] = (row < nrows)
            ? __ldg((const float4*)(g_XR + (r0 + row) * 256) + q)
            : make_float4(0.f, 0.f, 0.f, 0.f);
    }
    if (t < KB_ROWS) sgid[t] = (t < nrows) ? __ldg(gid + r0 + t) : -1;
    __syncthreads();

    if (nrows == 0) return;

    const int c  = t & 127;                  // output column
    const int rg = t >> 7;                   // row-group 0..3 (17 rows each)
    const float bb = __ldg(b1 + c);
    const float4* wp = (const float4*)(w1Ts + c * W1T_LD);

    float acc[17];
    #pragma unroll
    for (int r = 0; r < 17; ++r) acc[r] = 0.f;

    const float* xb = xs + (rg * 17) * 256;
    #pragma unroll 2
    for (int kq = 0; kq < 64; ++kq) {
        const float4 w = wp[kq];
        #pragma unroll
        for (int r = 0; r < 17; ++r) {
            const float4 x = *(const float4*)(xb + r * 256 + kq * 4);
            float a = acc[r];
            a = fmaf(x.x, w.x, a);
            a = fmaf(x.y, w.y, a);
            a = fmaf(x.z, w.z, a);
            a = fmaf(x.w, w.w, a);
            acc[r] = a;
        }
    }

    // relu + run-length coalesced atomics (gids sorted; pad rows gid=-1)
    int curg = sgid[rg * 17];
    float s = 0.f;
    #pragma unroll
    for (int r = 0; r < 17; ++r) {
        const int row = rg * 17 + r;
        if (row < nrows) {
            const float y = fmaxf(acc[r] + bb, 0.f);
            const int g = sgid[row];
            if (g != curg) {
                if (curg >= 0) atomicAdd(&g_Seg[curg * OUTD + c], s);
                s = 0.f; curg = g;
            }
            s += y;
        }
    }
    if (curg >= 0) atomicAdd(&g_Seg[curg * OUTD + c], s);
}

// ---------------------------------------------------------------------------
// Kernel C: readout MLP, one block per graph.
// ---------------------------------------------------------------------------
extern "C" __global__ void __launch_bounds__(64, 8)
kC(const float* __restrict__ wr1, const float* __restrict__ br1,
   const float* __restrict__ wr2, const float* __restrict__ br2,
   const float* __restrict__ wr3, const float* __restrict__ br3,
   float* __restrict__ out)
{
    __shared__ float r1s[35];
    __shared__ float r2s[35];
    const int g = blockIdx.x, t = threadIdx.x;
    const float SC = 1.0507009873554805f;
    const float AL = 1.6732632423543772f;

    if (t < 35) {
        float acc = br1[t];
        #pragma unroll 4
        for (int k = 0; k < OUTD; ++k)
            acc = fmaf(g_Seg[g * OUTD + k], wr1[k * 35 + t], acc);
        r1s[t] = (acc > 0.f) ? SC * acc : SC * AL * (expf(acc) - 1.f);
    }
    __syncthreads();

    if (t < 35) {
        float acc = br2[t];
        #pragma unroll
        for (int k = 0; k < 35; ++k)
            acc = fmaf(r1s[k], wr2[k * 35 + t], acc);
        r2s[t] = (acc > 0.f) ? SC * acc : SC * AL * (expf(acc) - 1.f);
    }
    __syncthreads();

    if (t == 0) {
        float acc = br3[0];
        #pragma unroll
        for (int k = 0; k < 35; ++k)
            acc = fmaf(r2s[k], wr3[k], acc);
        out[g] = acc;
    }
}

// ---------------------------------------------------------------------------
extern "C" void kernel_launch(void* const* d_in, const int* in_sizes, int n_in,
                              void* d_out, int out_size)
{
    const float* h0  = (const float*)d_in[0];
    const float* h1  = (const float*)d_in[1];
    const float* h2  = (const float*)d_in[2];
    const float* w0  = (const float*)d_in[3];
    const float* b0  = (const float*)d_in[4];
    const float* w1  = (const float*)d_in[5];
    const float* b1  = (const float*)d_in[6];
    const float* wr1 = (const float*)d_in[7];
    const float* br1 = (const float*)d_in[8];
    const float* wr2 = (const float*)d_in[9];
    const float* br2 = (const float*)d_in[10];
    const float* wr3 = (const float*)d_in[11];
    const float* br3 = (const float*)d_in[12];
    const int*   gid = (const int*)d_in[13];

    const int smA = (8 + 16896 + 128 + NSLOT * XS_PAIR) * 4;    // 113,184 B
    const int smB = (33280 + 17408 + 68) * 4;                   // 203,024 B
    cudaFuncSetAttribute(kA, cudaFuncAttributeMaxDynamicSharedMemorySize, smA);
    cudaFuncSetAttribute(kB, cudaFuncAttributeMaxDynamicSharedMemorySize, smB);

    kA<<<GRID, 384, smA>>>(h0, h1, h2, w0, b0);
    kB<<<GRID, 512, smB>>>(w1, b1, gid);
    kC<<<NGRAPH, 64>>>(wr1, br1, wr2, br2, wr3, br3, (float*)d_out);
}